// round 1
// baseline (speedup 1.0000x reference)
#include <cuda_runtime.h>
#include <cmath>
#include <cstdint>

#define N_LEVELS 16
#define N_POINTS 1048576
#define TBL_STRIDE 524288u   // 2^19 entries per level
#define OUT_COMPS 35         // 3 (x passthrough) + 16*2 feats
#define THREADS 256

struct Params {
    float res[N_LEVELS];
    unsigned hms[N_LEVELS];
    unsigned long long magic[N_LEVELS];
};

// Lemire fastmod: n % d for 32-bit n,d with M = 2^64/d + 1 (exact for all n < 2^32)
__device__ __forceinline__ unsigned fastmod(unsigned n, unsigned d, unsigned long long M) {
    unsigned long long low = M * (unsigned long long)n;
    return (unsigned)__umul64hi(low, (unsigned long long)d);
}

__global__ __launch_bounds__(THREADS)
void hashgrid_kernel(const float* __restrict__ x,
                     const float2* __restrict__ tables,
                     float* __restrict__ out,
                     Params prm) {
    __shared__ float stage[THREADS * OUT_COMPS];

    const int pt = blockIdx.x * THREADS + threadIdx.x;

    const float x0 = x[pt * 3 + 0];
    const float x1 = x[pt * 3 + 1];
    const float x2 = x[pt * 3 + 2];

    float* my = &stage[threadIdx.x * OUT_COMPS];
    my[0] = x0; my[1] = x1; my[2] = x2;

    const unsigned P1 = 2654435761u;
    const unsigned P2 = 805459861u;

#pragma unroll
    for (int l = 0; l < N_LEVELS; l++) {
        const float r = prm.res[l];
        const unsigned d = prm.hms[l];
        const unsigned long long M = prm.magic[l];
        const float2* __restrict__ tb = tables + (size_t)l * TBL_STRIDE;

        const float xs0 = x0 * r, xs1 = x1 * r, xs2 = x2 * r;
        const float fl0 = floorf(xs0), fl1 = floorf(xs1), fl2 = floorf(xs2);
        const float fx = xs0 - fl0, fy = xs1 - fl1, fz = xs2 - fl2;
        const int i0 = (int)fl0, i1 = (int)fl1, i2 = (int)fl2;

        // hash components per dim: dim0*1, dim1*P1, dim2*P2; +1 corner is additive
        unsigned ha[2], hb[2], hc[2];
        ha[0] = (unsigned)i0;        ha[1] = ha[0] + 1u;
        hb[0] = (unsigned)i1 * P1;   hb[1] = hb[0] + P1;
        hc[0] = (unsigned)i2 * P2;   hc[1] = hc[0] + P2;

        float wx[2], wy[2], wz[2];
        wx[0] = 1.0f - fx; wx[1] = fx;
        wy[0] = 1.0f - fy; wy[1] = fy;
        wz[0] = 1.0f - fz; wz[1] = fz;

        float acc0 = 0.0f, acc1 = 0.0f;
#pragma unroll
        for (int n = 0; n < 8; n++) {
            const int ix = n & 1, iy = (n >> 1) & 1, iz = (n >> 2) & 1;
            const unsigned h = ha[ix] ^ hb[iy] ^ hc[iz];
            const unsigned hm = fastmod(h, d, M);
            const float2 e = __ldg(&tb[hm]);
            const float w = wx[ix] * wy[iy] * wz[iz];
            acc0 = fmaf(e.x, w, acc0);
            acc1 = fmaf(e.y, w, acc1);
        }
        my[3 + 2 * l]     = acc0;
        my[3 + 2 * l + 1] = acc1;
    }

    __syncwarp();

    // Coalesced writeout: each warp copies its 32 rows (32*35 floats = 4480 B,
    // 16B-aligned both in smem and gmem) as float4.
    const int lane = threadIdx.x & 31;
    const int warp_first = (blockIdx.x * THREADS) + (threadIdx.x & ~31);
    const float4* src = (const float4*)&stage[(threadIdx.x & ~31) * OUT_COMPS];
    float4* dst = (float4*)(out + (size_t)warp_first * OUT_COMPS);
#pragma unroll
    for (int j = lane; j < (32 * OUT_COMPS) / 4; j += 32) {
        dst[j] = src[j];
    }
}

extern "C" void kernel_launch(void* const* d_in, const int* in_sizes, int n_in,
                              void* d_out, int out_size) {
    const float*  x      = (const float*)d_in[0];
    const float2* tables = (const float2*)d_in[1];
    float*        out    = (float*)d_out;

    // Level params computed with the exact same double-precision libm sequence
    // as the Python reference (same machine, same libm => bit-identical):
    //   beta = exp((log(2048) - log(16)) / 15); res[l] = floor(16 * beta**l)
    Params prm;
    const double beta = exp((log(2048.0) - log(16.0)) / 15.0);
    for (int l = 0; l < N_LEVELS; l++) {
        const double r = floor(16.0 * pow(beta, (double)l));
        prm.res[l] = (float)r;
        const long long ri = (long long)r;
        long long h3 = ri * ri * ri;
        if (h3 > 524288LL) h3 = 524288LL;
        const unsigned d = (unsigned)h3;
        prm.hms[l] = d;
        prm.magic[l] = 0xFFFFFFFFFFFFFFFFull / d + 1ull;
    }

    const int npts = in_sizes[0] / 3;
    const int blocks = (npts + THREADS - 1) / THREADS;
    hashgrid_kernel<<<blocks, THREADS>>>(x, tables, out, prm);
}

// round 2
// speedup vs baseline: 1.0083x; 1.0083x over previous
#include <cuda_runtime.h>
#include <cmath>
#include <cstdint>

#define N_LEVELS 16
#define TBL_STRIDE 524288u   // 2^19 entries per level
#define OUT_COMPS 35         // 3 (x passthrough) + 16*2 feats
#define THREADS 256
#define HASH_MASK 524287u    // 2^19 - 1, levels >= 6 are always fully hashed

struct Params {
    float res[N_LEVELS];
    unsigned hms[N_LEVELS];
    unsigned long long magic[N_LEVELS];
};

// Lemire fastmod: n % d with M = 2^64/d + 1 (exact for all n < 2^32)
__device__ __forceinline__ unsigned fastmod(unsigned n, unsigned d, unsigned long long M) {
    unsigned long long low = M * (unsigned long long)n;
    return (unsigned)__umul64hi(low, (unsigned long long)d);
}

__global__ __launch_bounds__(THREADS)
void hashgrid_kernel(const float* __restrict__ x,
                     const float2* __restrict__ tables,
                     float* __restrict__ out,
                     Params prm) {
    __shared__ float stage[THREADS * OUT_COMPS];

    const int pt = blockIdx.x * THREADS + threadIdx.x;

    const float x0 = x[pt * 3 + 0];
    const float x1 = x[pt * 3 + 1];
    const float x2 = x[pt * 3 + 2];

    float* my = &stage[threadIdx.x * OUT_COMPS];
    my[0] = x0; my[1] = x1; my[2] = x2;

    const unsigned P1 = 2654435761u;
    const unsigned P2 = 805459861u;

    // Process levels in pairs: issue all 16 gathers of (lp, lp+1) before
    // consuming either, doubling per-warp loads in flight.
#pragma unroll
    for (int lp = 0; lp < N_LEVELS; lp += 2) {
        unsigned hm[16];
        float wgt[2][3][2];   // [sub-level][dim][corner bit]

#pragma unroll
        for (int s = 0; s < 2; s++) {
            const int l = lp + s;
            const float r = prm.res[l];
            const float xs0 = x0 * r, xs1 = x1 * r, xs2 = x2 * r;
            const float fl0 = floorf(xs0), fl1 = floorf(xs1), fl2 = floorf(xs2);
            const float fx = xs0 - fl0, fy = xs1 - fl1, fz = xs2 - fl2;

            const unsigned a0 = (unsigned)(int)fl0;
            const unsigned b0 = (unsigned)(int)fl1 * P1;
            const unsigned c0 = (unsigned)(int)fl2 * P2;
            const unsigned ha[2] = {a0, a0 + 1u};
            const unsigned hb[2] = {b0, b0 + P1};
            const unsigned hc[2] = {c0, c0 + P2};

            wgt[s][0][0] = 1.0f - fx; wgt[s][0][1] = fx;
            wgt[s][1][0] = 1.0f - fy; wgt[s][1][1] = fy;
            wgt[s][2][0] = 1.0f - fz; wgt[s][2][1] = fz;

#pragma unroll
            for (int n = 0; n < 8; n++) {
                const unsigned h = ha[n & 1] ^ hb[(n >> 1) & 1] ^ hc[n >> 2];
                // Levels >= 6 always have hms == 2^19 (res >= 111): single AND.
                hm[s * 8 + n] = (l < 6) ? fastmod(h, prm.hms[l], prm.magic[l])
                                        : (h & HASH_MASK);
            }
        }

        float2 e[16];
#pragma unroll
        for (int n = 0; n < 16; n++) {
            const int l = lp + (n >> 3);
            const float2* p = tables + (size_t)l * TBL_STRIDE + hm[n];
            // L1-allocate only the small coarse tables (levels 0-2, ~333 KB);
            // big hashed tables go L2-only so they don't thrash L1.
            e[n] = (l < 3) ? __ldg(p) : __ldcg(p);
        }

#pragma unroll
        for (int s = 0; s < 2; s++) {
            float acc0 = 0.0f, acc1 = 0.0f;
#pragma unroll
            for (int n = 0; n < 8; n++) {
                const float w = wgt[s][0][n & 1] * wgt[s][1][(n >> 1) & 1] * wgt[s][2][n >> 2];
                acc0 = fmaf(e[s * 8 + n].x, w, acc0);
                acc1 = fmaf(e[s * 8 + n].y, w, acc1);
            }
            my[3 + 2 * (lp + s)]     = acc0;
            my[3 + 2 * (lp + s) + 1] = acc1;
        }
    }

    __syncwarp();

    // Coalesced writeout: each warp copies its 32 rows (32*35 floats = 4480 B,
    // 16B-aligned both in smem and gmem) as float4.
    const int lane = threadIdx.x & 31;
    const int warp_first = (blockIdx.x * THREADS) + (threadIdx.x & ~31);
    const float4* src = (const float4*)&stage[(threadIdx.x & ~31) * OUT_COMPS];
    float4* dst = (float4*)(out + (size_t)warp_first * OUT_COMPS);
#pragma unroll
    for (int j = lane; j < (32 * OUT_COMPS) / 4; j += 32) {
        dst[j] = src[j];
    }
}

extern "C" void kernel_launch(void* const* d_in, const int* in_sizes, int n_in,
                              void* d_out, int out_size) {
    const float*  x      = (const float*)d_in[0];
    const float2* tables = (const float2*)d_in[1];
    float*        out    = (float*)d_out;

    // Level params via the exact same double-precision libm sequence as the
    // Python reference (same machine/libm => bit-identical results).
    Params prm;
    const double beta = exp((log(2048.0) - log(16.0)) / 15.0);
    for (int l = 0; l < N_LEVELS; l++) {
        const double r = floor(16.0 * pow(beta, (double)l));
        prm.res[l] = (float)r;
        const long long ri = (long long)r;
        long long h3 = ri * ri * ri;
        if (h3 > 524288LL) h3 = 524288LL;
        const unsigned d = (unsigned)h3;
        prm.hms[l] = d;
        prm.magic[l] = 0xFFFFFFFFFFFFFFFFull / d + 1ull;
    }

    const int npts = in_sizes[0] / 3;
    const int blocks = (npts + THREADS - 1) / THREADS;
    hashgrid_kernel<<<blocks, THREADS>>>(x, tables, out, prm);
}

// round 3
// speedup vs baseline: 1.3130x; 1.3022x over previous
#include <cuda_runtime.h>
#include <cmath>
#include <cstdint>

#define N_LEVELS 16
#define TBL_STRIDE 524288u   // 2^19 entries per level
#define OUT_COMPS 35         // 3 (x passthrough) + 16*2 feats
#define THREADS 256
#define HASH_MASK 524287u    // 2^19 - 1; levels >= 6 are always fully hashed

struct Params {
    float res[N_LEVELS];
    unsigned hms[N_LEVELS];
    unsigned long long magic[N_LEVELS];
};

// Lemire fastmod: n % d with M = 2^64/d + 1 (exact for all n < 2^32)
__device__ __forceinline__ unsigned fastmod(unsigned n, unsigned d, unsigned long long M) {
    unsigned long long low = M * (unsigned long long)n;
    return (unsigned)__umul64hi(low, (unsigned long long)d);
}

__global__ __launch_bounds__(THREADS)
void hashgrid_kernel(const float* __restrict__ x,
                     const float2* __restrict__ tables,
                     float* __restrict__ out,
                     Params prm) {
    __shared__ float stage[THREADS * OUT_COMPS];

    const int pt = blockIdx.x * THREADS + threadIdx.x;

    const float x0 = x[pt * 3 + 0];
    const float x1 = x[pt * 3 + 1];
    const float x2 = x[pt * 3 + 2];

    float* my = &stage[threadIdx.x * OUT_COMPS];
    my[0] = x0; my[1] = x1; my[2] = x2;

    const unsigned P1 = 2654435761u;
    const unsigned P2 = 805459861u;

#pragma unroll
    for (int l = 0; l < N_LEVELS; l++) {
        const float r = prm.res[l];
        const float2* __restrict__ tb = tables + (size_t)l * TBL_STRIDE;

        const float xs0 = x0 * r, xs1 = x1 * r, xs2 = x2 * r;
        const float fl0 = floorf(xs0), fl1 = floorf(xs1), fl2 = floorf(xs2);
        const float fx = xs0 - fl0, fy = xs1 - fl1, fz = xs2 - fl2;

        const unsigned a0 = (unsigned)(int)fl0;
        const unsigned a1 = a0 + 1u;
        const unsigned b0 = (unsigned)(int)fl1 * P1;
        const unsigned c0 = (unsigned)(int)fl2 * P2;
        const unsigned hb[2] = {b0, b0 + P1};
        const unsigned hc[2] = {c0, c0 + P2};

        // e[n], n = ix | iy<<1 | iz<<2
        float2 e[8];

        if (l >= 6) {
            // Fully hashed: index = h & MASK. When a0 is even, h(ix=1) = h(ix=0)^1
            // for every (iy,iz) pair -> indices {2k,2k+1} -> one float4 load.
            if ((a0 & 1u) == 0u) {
#pragma unroll
                for (int p = 0; p < 4; p++) {
                    const int iy = p & 1, iz = p >> 1;
                    const unsigned m0 = (a0 ^ hb[iy] ^ hc[iz]) & HASH_MASK;
                    const float4 q = __ldcg((const float4*)tb + (m0 >> 1));
                    const float2 lo = make_float2(q.x, q.y);
                    const float2 hi = make_float2(q.z, q.w);
                    const bool odd = (m0 & 1u) != 0u;
                    const int n = (iy << 1) | (iz << 2);
                    e[n]     = odd ? hi : lo;   // corner ix=0 has index m0
                    e[n | 1] = odd ? lo : hi;   // corner ix=1 has index m0^1
                }
            } else {
#pragma unroll
                for (int p = 0; p < 4; p++) {
                    const int iy = p & 1, iz = p >> 1;
                    const unsigned hbc = hb[iy] ^ hc[iz];
                    const int n = (iy << 1) | (iz << 2);
                    e[n]     = __ldcg(tb + ((a0 ^ hbc) & HASH_MASK));
                    e[n | 1] = __ldcg(tb + ((a1 ^ hbc) & HASH_MASK));
                }
            }
        } else {
            const unsigned d = prm.hms[l];
            const unsigned long long M = prm.magic[l];
#pragma unroll
            for (int p = 0; p < 4; p++) {
                const int iy = p & 1, iz = p >> 1;
                const unsigned hbc = hb[iy] ^ hc[iz];
                const unsigned m0 = fastmod(a0 ^ hbc, d, M);
                const unsigned m1 = fastmod(a1 ^ hbc, d, M);
                const int n = (iy << 1) | (iz << 2);
                if ((m0 ^ m1) == 1u) {
                    // Same aligned 16B pair: merge into one float4 load.
                    const float4 q = (l < 3) ? __ldg((const float4*)tb + (m0 >> 1))
                                             : __ldcg((const float4*)tb + (m0 >> 1));
                    const float2 lo = make_float2(q.x, q.y);
                    const float2 hi = make_float2(q.z, q.w);
                    const bool odd = (m0 & 1u) != 0u;
                    e[n]     = odd ? hi : lo;
                    e[n | 1] = odd ? lo : hi;
                } else {
                    e[n]     = (l < 3) ? __ldg(tb + m0) : __ldcg(tb + m0);
                    e[n | 1] = (l < 3) ? __ldg(tb + m1) : __ldcg(tb + m1);
                }
            }
        }

        const float wx[2] = {1.0f - fx, fx};
        const float wy[2] = {1.0f - fy, fy};
        const float wz[2] = {1.0f - fz, fz};

        float acc0 = 0.0f, acc1 = 0.0f;
#pragma unroll
        for (int n = 0; n < 8; n++) {
            const float w = wx[n & 1] * wy[(n >> 1) & 1] * wz[n >> 2];
            acc0 = fmaf(e[n].x, w, acc0);
            acc1 = fmaf(e[n].y, w, acc1);
        }
        my[3 + 2 * l]     = acc0;
        my[3 + 2 * l + 1] = acc1;
    }

    __syncwarp();

    // Coalesced writeout: each warp copies its 32 rows (32*35 floats = 4480 B,
    // 16B-aligned in smem and gmem) as float4.
    const int lane = threadIdx.x & 31;
    const int warp_first = (blockIdx.x * THREADS) + (threadIdx.x & ~31);
    const float4* src = (const float4*)&stage[(threadIdx.x & ~31) * OUT_COMPS];
    float4* dst = (float4*)(out + (size_t)warp_first * OUT_COMPS);
#pragma unroll
    for (int j = lane; j < (32 * OUT_COMPS) / 4; j += 32) {
        dst[j] = src[j];
    }
}

extern "C" void kernel_launch(void* const* d_in, const int* in_sizes, int n_in,
                              void* d_out, int out_size) {
    const float*  x      = (const float*)d_in[0];
    const float2* tables = (const float2*)d_in[1];
    float*        out    = (float*)d_out;

    // Level params via the exact same double-precision libm sequence as the
    // Python reference (same machine/libm => bit-identical results).
    Params prm;
    const double beta = exp((log(2048.0) - log(16.0)) / 15.0);
    for (int l = 0; l < N_LEVELS; l++) {
        const double r = floor(16.0 * pow(beta, (double)l));
        prm.res[l] = (float)r;
        const long long ri = (long long)r;
        long long h3 = ri * ri * ri;
        if (h3 > 524288LL) h3 = 524288LL;
        const unsigned d = (unsigned)h3;
        prm.hms[l] = d;
        prm.magic[l] = 0xFFFFFFFFFFFFFFFFull / d + 1ull;
    }

    const int npts = in_sizes[0] / 3;
    const int blocks = (npts + THREADS - 1) / THREADS;
    hashgrid_kernel<<<blocks, THREADS>>>(x, tables, out, prm);
}